// round 12
// baseline (speedup 1.0000x reference)
#include <cuda_runtime.h>
#include <cuda_bf16.h>
#include <math.h>
#include <stdint.h>

// ---------------- problem constants ----------------
#define B_  16
#define S_  1024
#define E_  512
#define L_  2048      // P*G
#define HD_ 256
#define SCALE_ 0.0625f
#define LAMBDA_INIT_ 0.2f
#define ONE_MINUS_LI_ 0.8f

typedef __nv_bfloat16 bf16;

// ---------------- device scratch (no allocs allowed) ----------------
__device__ float g_S [(size_t)B_*2*S_*L_];    // scores (compact rows per (b,h))
__device__ float g_O2[(size_t)B_*S_*E_];      // out2d fp32
__device__ float g_lam;
__device__ unsigned char g_mask[B_*S_];
__device__ int g_mask_mode;
__device__ int g_idx[B_*S_];                  // compact i -> s (per batch)
__device__ int g_cnt[B_];                     // unmasked count per batch
__device__ float g_km[B_*E_];                 // mean over L of key2d
__device__ float g_mV[B_*E_];                 // mean over L of V rows

// bf16 split operand buffers (hi / lo)
__device__ bf16 g_qh[(size_t)B_*S_*E_],  g_ql[(size_t)B_*S_*E_];   // compacted query
__device__ bf16 g_kh[(size_t)B_*L_*E_],  g_kl[(size_t)B_*L_*E_];
__device__ bf16 g_Wqh[E_*E_], g_Wql[E_*E_], g_Wkh[E_*E_], g_Wkl[E_*E_];
__device__ bf16 g_Wvh[E_*E_], g_Wvl[E_*E_], g_Woh[E_*E_], g_Wol[E_*E_];
__device__ bf16 g_Qh[(size_t)B_*S_*E_],  g_Ql[(size_t)B_*S_*E_];   // compact Q (scaled)
__device__ bf16 g_Kh[(size_t)B_*L_*E_],  g_Kl[(size_t)B_*L_*E_];
__device__ bf16 g_Vth[(size_t)E_*B_*L_], g_Vtl[(size_t)E_*B_*L_];  // V^T [E][B*L]
__device__ bf16 g_dh[(size_t)B_*S_*L_],  g_dl[(size_t)B_*S_*L_];   // compact diff
__device__ bf16 g_rh[(size_t)B_*S_*E_],  g_rl[(size_t)B_*S_*E_];

// ---------------- small helpers ----------------
__device__ __forceinline__ float warpSum(float v) {
#pragma unroll
    for (int o = 16; o; o >>= 1) v += __shfl_xor_sync(0xffffffffu, v, o);
    return v;
}
__device__ __forceinline__ float warpMax(float v) {
#pragma unroll
    for (int o = 16; o; o >>= 1) v = fmaxf(v, __shfl_xor_sync(0xffffffffu, v, o));
    return v;
}
__device__ __forceinline__ void splitf(float x, bf16& h, bf16& l) {
    h = __float2bfloat16(x);
    l = __float2bfloat16(x - __bfloat162float(h));
}
__device__ __forceinline__ uint32_t s2u(const void* p) {
    return (uint32_t)__cvta_generic_to_shared(p);
}

// ---------------- tensor-core primitives (sm_80 baseline ISA) ----------------
__device__ __forceinline__ void ldsm_x4(uint32_t& r0, uint32_t& r1, uint32_t& r2,
                                        uint32_t& r3, uint32_t addr) {
    asm volatile("ldmatrix.sync.aligned.m8n8.x4.shared.b16 {%0,%1,%2,%3}, [%4];"
                 : "=r"(r0), "=r"(r1), "=r"(r2), "=r"(r3) : "r"(addr));
}
__device__ __forceinline__ void ldsm_x2(uint32_t& r0, uint32_t& r1, uint32_t addr) {
    asm volatile("ldmatrix.sync.aligned.m8n8.x2.shared.b16 {%0,%1}, [%2];"
                 : "=r"(r0), "=r"(r1) : "r"(addr));
}
__device__ __forceinline__ void mma16816(float* c, const uint32_t* a, const uint32_t* b) {
    asm volatile(
        "mma.sync.aligned.m16n8k16.row.col.f32.bf16.bf16.f32 "
        "{%0,%1,%2,%3}, {%4,%5,%6,%7}, {%8,%9}, {%0,%1,%2,%3};"
        : "+f"(c[0]), "+f"(c[1]), "+f"(c[2]), "+f"(c[3])
        : "r"(a[0]), "r"(a[1]), "r"(a[2]), "r"(a[3]), "r"(b[0]), "r"(b[1]));
}
__device__ __forceinline__ void cp16(uint32_t dst, const void* src) {
    asm volatile("cp.async.cg.shared.global [%0], [%1], 16;" :: "r"(dst), "l"(src));
}

// ---------------- GEMM config ----------------
#define BM 128
#define BN 128
#define BKT 32
#define SROW 40   // padded smem row stride (elems)

// C[M,N] = alpha * sum over 3 passes of Ap[M,K] @ Bp[N,K]^T  (bf16 in, fp32 accum)
// passes: (Ahi,Bhi), (Alo,Bhi), (Ahi,Blo)
// mode 0: fp32 -> Cf.  mode 1: bf16 split -> Ohi/Olo.  mode 2: bf16 split transposed.
// cnts (per zo): valid output rows; blocks with m0 >= cnts[zo] exit; row writes guarded.
// rowmap (per zo, stride S_): output row scatter (mode 0 only).
__global__ void __launch_bounds__(256, 2)
gemm3_kernel(const bf16* __restrict__ Ahi, const bf16* __restrict__ Alo,
             const bf16* __restrict__ Bhi, const bf16* __restrict__ Blo,
             float* __restrict__ Cf, bf16* __restrict__ Ohi, bf16* __restrict__ Olo,
             int K, int lda, int ldb, int ldout,
             int zdiv, long long sAo, long long sAi, long long sBo, long long sBi,
             long long sCo, long long sCi, float alpha, int mode,
             const int* __restrict__ cnts, const int* __restrict__ rowmap)
{
    __shared__ __align__(16) bf16 sA[2][BM * SROW];
    __shared__ __align__(16) bf16 sB[2][BN * SROW];

    const int tid  = threadIdx.x;
    const int lane = tid & 31;
    const int wid  = tid >> 5;
    const int wm   = wid & 1;
    const int wn   = wid >> 1;
    const int m0 = blockIdx.y * BM;
    const int n0 = blockIdx.x * BN;
    const int z  = blockIdx.z;
    const int zo = z / zdiv, zi = z - zo * zdiv;

    const int cnt = cnts ? cnts[zo] : 0x7fffffff;
    if (m0 >= cnt) return;

    const long long aoff = zo * sAo + zi * sAi;
    const long long boff = zo * sBo + zi * sBi;
    const long long coff = zo * sCo + zi * sCi;
    Ahi += aoff; Alo += aoff; Bhi += boff; Blo += boff;

    const int ktiles = K / BKT;
    const int total  = 3 * ktiles;

    float acc[4][4][4];
#pragma unroll
    for (int mi = 0; mi < 4; mi++)
#pragma unroll
        for (int ni = 0; ni < 4; ni++)
#pragma unroll
            for (int r = 0; r < 4; r++) acc[mi][ni][r] = 0.f;

    auto issue = [&](int it, int buf) {
        const int p  = it / ktiles;
        const int kt = it - p * ktiles;
        const bf16* Ap = ((p == 1) ? Alo : Ahi) + (long long)m0 * lda + kt * BKT;
        const bf16* Bp = ((p == 2) ? Blo : Bhi) + (long long)n0 * ldb + kt * BKT;
#pragma unroll
        for (int i = 0; i < 2; i++) {
            int u = tid + i * 256;
            int row = u >> 2, kc = (u & 3) * 8;
            cp16(s2u(&sA[buf][row * SROW + kc]), Ap + (long long)row * lda + kc);
            cp16(s2u(&sB[buf][row * SROW + kc]), Bp + (long long)row * ldb + kc);
        }
        asm volatile("cp.async.commit_group;" ::: "memory");
    };

    issue(0, 0);
    for (int it = 0; it < total; it++) {
        const int cur = it & 1;
        if (it + 1 < total) {
            issue(it + 1, cur ^ 1);
            asm volatile("cp.async.wait_group 1;" ::: "memory");
        } else {
            asm volatile("cp.async.wait_group 0;" ::: "memory");
        }
        __syncthreads();

        const bf16* sa = sA[cur];
        const bf16* sb = sB[cur];
#pragma unroll
        for (int ks = 0; ks < 2; ks++) {
            uint32_t af[4][4], bfr[4][2];
            const int arow = wm * 64 + (lane & 15);
            const int acol = ks * 16 + (lane >> 4) * 8;
#pragma unroll
            for (int mi = 0; mi < 4; mi++)
                ldsm_x4(af[mi][0], af[mi][1], af[mi][2], af[mi][3],
                        s2u(sa + (arow + mi * 16) * SROW + acol));
            const int brow = wn * 32 + (lane & 7);
            const int bcol = ks * 16 + ((lane >> 3) & 1) * 8;
#pragma unroll
            for (int ni = 0; ni < 4; ni++)
                ldsm_x2(bfr[ni][0], bfr[ni][1],
                        s2u(sb + (brow + ni * 8) * SROW + bcol));
#pragma unroll
            for (int mi = 0; mi < 4; mi++)
#pragma unroll
                for (int ni = 0; ni < 4; ni++)
                    mma16816(acc[mi][ni], af[mi], bfr[ni]);
        }
        __syncthreads();
    }

    // ---- epilogue ----
    const int g = lane >> 2, tg = lane & 3;
    const int* rmap = rowmap ? (rowmap + (long long)zo * S_) : nullptr;
#pragma unroll
    for (int mi = 0; mi < 4; mi++) {
#pragma unroll
        for (int ni = 0; ni < 4; ni++) {
            const int r0  = m0 + wm * 64 + mi * 16 + g;
            const int r1  = r0 + 8;
            const int col = n0 + wn * 32 + ni * 8 + 2 * tg;
            float c0 = alpha * acc[mi][ni][0];
            float c1 = alpha * acc[mi][ni][1];
            float c2 = alpha * acc[mi][ni][2];
            float c3 = alpha * acc[mi][ni][3];
            if (mode == 0) {
                if (r0 < cnt) {
                    int ro = rmap ? rmap[r0] : r0;
                    *(float2*)(Cf + coff + (long long)ro * ldout + col) = make_float2(c0, c1);
                }
                if (r1 < cnt) {
                    int ro = rmap ? rmap[r1] : r1;
                    *(float2*)(Cf + coff + (long long)ro * ldout + col) = make_float2(c2, c3);
                }
            } else if (mode == 1) {
                bf16 h0, l0, h1, l1, h2, l2, h3, l3;
                splitf(c0, h0, l0); splitf(c1, h1, l1);
                splitf(c2, h2, l2); splitf(c3, h3, l3);
                if (r0 < cnt) {
                    __nv_bfloat162 hv; hv.x = h0; hv.y = h1;
                    __nv_bfloat162 lv; lv.x = l0; lv.y = l1;
                    *(__nv_bfloat162*)(Ohi + coff + (long long)r0 * ldout + col) = hv;
                    *(__nv_bfloat162*)(Olo + coff + (long long)r0 * ldout + col) = lv;
                }
                if (r1 < cnt) {
                    __nv_bfloat162 hv; hv.x = h2; hv.y = h3;
                    __nv_bfloat162 lv; lv.x = l2; lv.y = l3;
                    *(__nv_bfloat162*)(Ohi + coff + (long long)r1 * ldout + col) = hv;
                    *(__nv_bfloat162*)(Olo + coff + (long long)r1 * ldout + col) = lv;
                }
            } else {
                bf16 h, l;
                splitf(c0, h, l);
                Ohi[coff + (long long)col * ldout + r0] = h;
                Olo[coff + (long long)col * ldout + r0] = l;
                splitf(c1, h, l);
                Ohi[coff + (long long)(col + 1) * ldout + r0] = h;
                Olo[coff + (long long)(col + 1) * ldout + r0] = l;
                splitf(c2, h, l);
                Ohi[coff + (long long)col * ldout + r1] = h;
                Olo[coff + (long long)col * ldout + r1] = l;
                splitf(c3, h, l);
                Ohi[coff + (long long)(col + 1) * ldout + r1] = h;
                Olo[coff + (long long)(col + 1) * ldout + r1] = l;
            }
        }
    }
}

// ---------------- mask dtype detection + canonicalization ----------------
__global__ void mask_detect_kernel(const unsigned char* __restrict__ m) {
    int t = threadIdx.x;
    int nz1 = 0, nz23 = 0;
    for (int i = t; i < B_ * S_; i += 256) {
        unsigned char v = m[i];
        int r = i & 3;
        if (v) {
            if (r == 1) nz1 = 1;
            if (r == 2 || r == 3) nz23 = 1;
        }
    }
    nz1  = __syncthreads_or(nz1);
    nz23 = __syncthreads_or(nz23);
    if (t == 0) g_mask_mode = nz1 ? 0 : (nz23 ? 2 : 1);
}
__global__ void mask_convert_kernel(const void* __restrict__ m) {
    int i = blockIdx.x * 256 + threadIdx.x;
    int mode = g_mask_mode;
    unsigned char v;
    if (mode == 0)      v = ((const unsigned char*)m)[i] != 0;
    else if (mode == 1) v = ((const int*)m)[i] != 0;
    else                v = ((const float*)m)[i] != 0.0f;
    g_mask[i] = v;
}

// ---------------- per-batch compaction of unmasked rows ----------------
__global__ void compact_kernel() {
    const int b = blockIdx.x, s = threadIdx.x;     // 1024 threads
    const int lane = s & 31, w = s >> 5;
    __shared__ int wcnt[32];
    int f = g_mask[b * S_ + s] ? 1 : 0;
    unsigned bal = __ballot_sync(0xffffffffu, f);
    int lanePre = __popc(bal & ((1u << lane) - 1u));
    if (lane == 0) wcnt[w] = __popc(bal);
    __syncthreads();
    if (w == 0) {
        int v = wcnt[lane];
#pragma unroll
        for (int o = 1; o < 32; o <<= 1) {
            int u = __shfl_up_sync(0xffffffffu, v, o);
            if (lane >= o) v += u;
        }
        wcnt[lane] = v;   // inclusive scan
    }
    __syncthreads();
    int base = (w == 0) ? 0 : wcnt[w - 1];
    if (f) g_idx[b * S_ + base + lanePre] = s;
    if (s == 0) g_cnt[b] = wcnt[31];
}

// ---------------- gather + split query rows (compact) ----------------
__global__ void gather_split_q(const float* __restrict__ q) {
    const int blk = blockIdx.x;               // B*S
    const int b = blk >> 10, i = blk & (S_ - 1);
    if (i >= g_cnt[b]) return;
    const int s = g_idx[b * S_ + i];
    const float* src = q + ((size_t)b * S_ + s) * E_;
    bf16* dh = g_qh + ((size_t)b * S_ + i) * E_;
    bf16* dl = g_ql + ((size_t)b * S_ + i) * E_;
    const int t = threadIdx.x;                // 128
#pragma unroll
    for (int j = 0; j < 4; j++) {
        bf16 h, l; splitf(src[t + j * 128], h, l);
        dh[t + j * 128] = h; dl[t + j * 128] = l;
    }
}

// ---------------- elementwise split (fp32 -> bf16 hi/lo) ----------------
__global__ void split_kernel(const float* __restrict__ x, bf16* __restrict__ hi,
                             bf16* __restrict__ lo, long long n) {
    long long i = (long long)blockIdx.x * 256 + threadIdx.x;
    long long stride = (long long)gridDim.x * 256;
    for (; i < n; i += stride) {
        bf16 h, l; splitf(x[i], h, l);
        hi[i] = h; lo[i] = l;
    }
}
// split + transpose for 512x512 weights: T[n][k] = W[k][n]
__global__ void splitT_W_kernel(const float* __restrict__ W, bf16* __restrict__ Thi,
                                bf16* __restrict__ Tlo) {
    int idx = blockIdx.x * 256 + threadIdx.x;
    int n = idx >> 9, k = idx & 511;
    bf16 h, l; splitf(W[k * E_ + n], h, l);
    Thi[(long long)n * E_ + k] = h;
    Tlo[(long long)n * E_ + k] = l;
}

// ---------------- lambda ----------------
__global__ void lam_kernel(const float* __restrict__ lq1, const float* __restrict__ lk1,
                           const float* __restrict__ lq2, const float* __restrict__ lk2)
{
    __shared__ float sm[16];
    int t = threadIdx.x;
    float p1 = lq1[t] * lk1[t];
    float p2 = lq2[t] * lk2[t];
    p1 = warpSum(p1);
    p2 = warpSum(p2);
    int w = t >> 5, l = t & 31;
    if (l == 0) { sm[w] = p1; sm[8 + w] = p2; }
    __syncthreads();
    if (t == 0) {
        float d1 = 0.f, d2 = 0.f;
#pragma unroll
        for (int i = 0; i < 8; i++) { d1 += sm[i]; d2 += sm[8 + i]; }
        g_lam = expf(d1) - expf(d2) + LAMBDA_INIT_;
    }
}

// ---------------- key mean + masked out2d row value ----------------
__global__ void keymean_kernel(const float* __restrict__ key) {
    int id = blockIdx.x * 128 + threadIdx.x;   // B*E
    int b = id >> 9, e = id & 511;
    const float* p = key + (size_t)b * L_ * E_ + e;
    float s = 0.f;
    for (int l = 0; l < L_; l++) s += p[(size_t)l * E_];
    g_km[id] = s * (1.0f / (float)L_);
}
__global__ void mV_kernel(const float* __restrict__ Wv) {
    int id = blockIdx.x * 128 + threadIdx.x;   // B*E
    int b = id >> 9, e = id & 511;
    float s = 0.f;
    const float* km = g_km + b * E_;
    for (int k = 0; k < E_; k++) s += km[k] * Wv[k * E_ + e];
    g_mV[id] = s;
}

// ---------------- fused dual softmax + lambda-diff (compact rows only) ----------------
__global__ void __launch_bounds__(256)
softmax_diff_kernel(const float* __restrict__ sc, float* __restrict__ diff)
{
    __shared__ float sm[8];
    const int blk = blockIdx.x;                 // b*S + i (compact)
    const int b = blk >> 10;
    const int i = blk & (S_ - 1);
    if (i >= g_cnt[b]) return;
    const int s = g_idx[b * S_ + i];
    const int t = threadIdx.x;
    const int w = t >> 5, l = t & 31;
    const float lam = g_lam;
    float* out = diff + ((size_t)b * S_ + s) * L_;        // scattered fp32 output
    bf16* dh = g_dh + ((size_t)b * S_ + i) * L_;          // compact split for GEMM
    bf16* dl = g_dl + ((size_t)b * S_ + i) * L_;

    const float* r0 = sc + ((size_t)(2 * b + 0) * S_ + i) * L_;
    const float* r1 = sc + ((size_t)(2 * b + 1) * S_ + i) * L_;
    float e0[8], e1[8];

    float mx = -1e30f;
#pragma unroll
    for (int j = 0; j < 8; j++) { e0[j] = r0[t + j * 256]; mx = fmaxf(mx, e0[j]); }
    mx = warpMax(mx);
    if (l == 0) sm[w] = mx;
    __syncthreads();
#pragma unroll
    for (int j = 0; j < 8; j++) mx = fmaxf(mx, sm[j]);
    float sum0 = 0.f;
#pragma unroll
    for (int j = 0; j < 8; j++) { e0[j] = __expf(e0[j] - mx); sum0 += e0[j]; }
    sum0 = warpSum(sum0);
    __syncthreads();
    if (l == 0) sm[w] = sum0;
    __syncthreads();
    sum0 = 0.f;
#pragma unroll
    for (int j = 0; j < 8; j++) sum0 += sm[j];
    const float inv0 = 1.0f / sum0;

    float mx1 = -1e30f;
#pragma unroll
    for (int j = 0; j < 8; j++) { e1[j] = r1[t + j * 256]; mx1 = fmaxf(mx1, e1[j]); }
    mx1 = warpMax(mx1);
    __syncthreads();
    if (l == 0) sm[w] = mx1;
    __syncthreads();
#pragma unroll
    for (int j = 0; j < 8; j++) mx1 = fmaxf(mx1, sm[j]);
    float sum1 = 0.f;
#pragma unroll
    for (int j = 0; j < 8; j++) { e1[j] = __expf(e1[j] - mx1); sum1 += e1[j]; }
    sum1 = warpSum(sum1);
    __syncthreads();
    if (l == 0) sm[w] = sum1;
    __syncthreads();
    sum1 = 0.f;
#pragma unroll
    for (int j = 0; j < 8; j++) sum1 += sm[j];
    const float inv1 = 1.0f / sum1;

#pragma unroll
    for (int j = 0; j < 8; j++) {
        float v = e0[j] * inv0 - lam * (e1[j] * inv1);
        out[t + j * 256] = v;
        bf16 h, lo; splitf(v, h, lo);
        dh[t + j * 256] = h; dl[t + j * 256] = lo;
    }
}

// ---------------- masked rows: diff const + out2d = (1-lam)*meanV[b] ----------------
__global__ void __launch_bounds__(256)
fill_masked_kernel(float* __restrict__ diff)
{
    const int bs = blockIdx.x;
    if (g_mask[bs]) return;
    const int b = bs >> 10;
    const int t = threadIdx.x;
    const float oml = 1.0f - g_lam;
    const float v = oml * (1.0f / (float)L_);
    float* dr = diff + (size_t)bs * L_;
#pragma unroll
    for (int j = 0; j < 8; j++) dr[t + j * 256] = v;
    float* orow = g_O2 + (size_t)bs * E_;
    orow[t]       = oml * g_mV[b * E_ + t];
    orow[t + 256] = oml * g_mV[b * E_ + t + 256];
}

// ---------------- RMSNorm * gamma * 0.8 -> bf16 split ----------------
__global__ void __launch_bounds__(128)
rmsnorm_kernel(const float* __restrict__ x, const float* __restrict__ gamma)
{
    __shared__ float sm[4];
    const int row = blockIdx.x;
    const int t = threadIdx.x;
    const float4 v = ((const float4*)(x + (size_t)row * E_))[t];
    float ss = v.x * v.x + v.y * v.y + v.z * v.z + v.w * v.w;
    ss = warpSum(ss);
    int w = t >> 5, l = t & 31;
    if (l == 0) sm[w] = ss;
    __syncthreads();
    ss = sm[0] + sm[1] + sm[2] + sm[3];
    float r = rsqrtf(ss * (1.0f / (float)E_) + 1e-5f) * ONE_MINUS_LI_;
    float4 g = ((const float4*)gamma)[t];
    float y[4] = {v.x * r * g.x, v.y * r * g.y, v.z * r * g.z, v.w * r * g.w};
    bf16* oh = g_rh + (size_t)row * E_ + t * 4;
    bf16* ol = g_rl + (size_t)row * E_ + t * 4;
#pragma unroll
    for (int j = 0; j < 4; j++) {
        bf16 h, lo; splitf(y[j], h, lo);
        oh[j] = h; ol[j] = lo;
    }
}

// ---------------- launch ----------------
extern "C" void kernel_launch(void* const* d_in, const int* in_sizes, int n_in,
                              void* d_out, int out_size)
{
    const float* query = (const float*)d_in[0];
    const float* key   = (const float*)d_in[1];
    const void*  mask  = d_in[2];
    const float* Wq    = (const float*)d_in[3];
    const float* Wk    = (const float*)d_in[4];
    const float* Wv    = (const float*)d_in[5];
    const float* Wo    = (const float*)d_in[6];
    const float* lq1   = (const float*)d_in[7];
    const float* lk1   = (const float*)d_in[8];
    const float* lq2   = (const float*)d_in[9];
    const float* lk2   = (const float*)d_in[10];
    const float* gamma = (const float*)d_in[11];

    float* out  = (float*)d_out;
    float* diff = out + (size_t)B_ * S_ * E_;

    float *Sp, *Op;
    int *idxP, *cntP;
    bf16 *qh,*ql,*kh,*kl,*Wqh,*Wql,*Wkh,*Wkl,*Wvh,*Wvl,*Woh,*Wol;
    bf16 *Qh,*Ql,*Kh,*Kl,*Vth,*Vtl,*dh,*dl,*rh,*rl;
    cudaGetSymbolAddress((void**)&Sp,  g_S);
    cudaGetSymbolAddress((void**)&Op,  g_O2);
    cudaGetSymbolAddress((void**)&idxP, g_idx);
    cudaGetSymbolAddress((void**)&cntP, g_cnt);
    cudaGetSymbolAddress((void**)&qh,  g_qh);  cudaGetSymbolAddress((void**)&ql,  g_ql);
    cudaGetSymbolAddress((void**)&kh,  g_kh);  cudaGetSymbolAddress((void**)&kl,  g_kl);
    cudaGetSymbolAddress((void**)&Wqh, g_Wqh); cudaGetSymbolAddress((void**)&Wql, g_Wql);
    cudaGetSymbolAddress((void**)&Wkh, g_Wkh); cudaGetSymbolAddress((void**)&Wkl, g_Wkl);
    cudaGetSymbolAddress((void**)&Wvh, g_Wvh); cudaGetSymbolAddress((void**)&Wvl, g_Wvl);
    cudaGetSymbolAddress((void**)&Woh, g_Woh); cudaGetSymbolAddress((void**)&Wol, g_Wol);
    cudaGetSymbolAddress((void**)&Qh,  g_Qh);  cudaGetSymbolAddress((void**)&Ql,  g_Ql);
    cudaGetSymbolAddress((void**)&Kh,  g_Kh);  cudaGetSymbolAddress((void**)&Kl,  g_Kl);
    cudaGetSymbolAddress((void**)&Vth, g_Vth); cudaGetSymbolAddress((void**)&Vtl, g_Vtl);
    cudaGetSymbolAddress((void**)&dh,  g_dh);  cudaGetSymbolAddress((void**)&dl,  g_dl);
    cudaGetSymbolAddress((void**)&rh,  g_rh);  cudaGetSymbolAddress((void**)&rl,  g_rl);

    const long long SE = (long long)S_ * E_;
    const long long LE = (long long)L_ * E_;
    const long long SL = (long long)S_ * L_;
    const int BL = B_ * L_;   // 32768

    // mask, compaction, lambda
    mask_detect_kernel<<<1, 256>>>((const unsigned char*)mask);
    mask_convert_kernel<<<(B_ * S_) / 256, 256>>>(mask);
    compact_kernel<<<B_, S_>>>();
    lam_kernel<<<1, 256>>>(lq1, lk1, lq2, lk2);

    // input splits
    gather_split_q<<<B_ * S_, 128>>>(query);
    split_kernel<<<4096, 256>>>(key, kh, kl, (long long)B_ * L_ * E_);
    splitT_W_kernel<<<(E_ * E_) / 256, 256>>>(Wq, Wqh, Wql);
    splitT_W_kernel<<<(E_ * E_) / 256, 256>>>(Wk, Wkh, Wkl);
    splitT_W_kernel<<<(E_ * E_) / 256, 256>>>(Wv, Wvh, Wvl);
    splitT_W_kernel<<<(E_ * E_) / 256, 256>>>(Wo, Woh, Wol);

    // masked-row closed form ingredients
    keymean_kernel<<<(B_ * E_) / 128, 128>>>(key);
    mV_kernel<<<(B_ * E_) / 128, 128>>>(Wv);

    // Q proj (compact rows, per-batch z): -> split Qs (pre-scaled)
    gemm3_kernel<<<dim3(E_ / BN, S_ / BM, B_), 256>>>(
        qh, ql, Wqh, Wql, nullptr, Qh, Ql,
        E_, E_, E_, E_, 1, SE, 0, 0, 0, SE, 0, SCALE_, 1, cntP, nullptr);

    // K proj -> split Ks (full)
    gemm3_kernel<<<dim3(E_ / BN, (B_ * L_) / BM, 1), 256>>>(
        kh, kl, Wkh, Wkl, nullptr, Kh, Kl,
        E_, E_, E_, E_, 1, 0, 0, 0, 0, 0, 0, 1.0f, 1, nullptr, nullptr);

    // V proj -> transposed split Vt [E][B*L] (full)
    gemm3_kernel<<<dim3(E_ / BN, (B_ * L_) / BM, 1), 256>>>(
        kh, kl, Wvh, Wvl, nullptr, Vth, Vtl,
        E_, E_, E_, BL, 1, 0, 0, 0, 0, 0, 0, 1.0f, 2, nullptr, nullptr);

    // scores[b,h] = Qc[b,:,hHD:] @ K[b,:,hHD:]^T -> g_S (compact rows)
    gemm3_kernel<<<dim3(L_ / BN, S_ / BM, B_ * 2), 256>>>(
        Qh, Ql, Kh, Kl, Sp, nullptr, nullptr,
        HD_, E_, E_, L_, 2, SE, HD_, LE, HD_, 2 * SL, SL, 1.0f, 0, cntP, nullptr);

    // softmax + diff on compact rows (fp32 scattered to d_out, split compact)
    softmax_diff_kernel<<<B_ * S_, 256>>>(Sp, diff);

    // masked rows: diff const + out2d closed form
    fill_masked_kernel<<<B_ * S_, 256>>>(diff);

    // out2d[b] = diff_c[b] @ V[b] -> g_O2 fp32, rows scattered via g_idx
    gemm3_kernel<<<dim3(E_ / BN, S_ / BM, B_), 256>>>(
        dh, dl, Vth, Vtl, Op, nullptr, nullptr,
        L_, L_, BL, E_, 1, SL, 0, L_, 0, SE, 0, 1.0f, 0, cntP, idxP);

    // RMSNorm * gamma * 0.8 -> split rms (full S)
    rmsnorm_kernel<<<B_ * S_, 128>>>(Op, gamma);

    // out = rms @ Wo^T -> d_out fp32 (full)
    gemm3_kernel<<<dim3(E_ / BN, (B_ * S_) / BM, 1), 256>>>(
        rh, rl, Woh, Wol, out, nullptr, nullptr,
        E_, E_, E_, E_, 1, 0, 0, 0, 0, 0, 0, 1.0f, 0, nullptr, nullptr);
}

// round 13
// speedup vs baseline: 1.0104x; 1.0104x over previous
#include <cuda_runtime.h>
#include <cuda_bf16.h>
#include <math.h>
#include <stdint.h>

// ---------------- problem constants ----------------
#define B_  16
#define S_  1024
#define E_  512
#define L_  2048      // P*G
#define HD_ 256
#define SCALE_ 0.0625f
#define LAMBDA_INIT_ 0.2f
#define ONE_MINUS_LI_ 0.8f

typedef __nv_bfloat16 bf16;

// ---------------- device scratch (no allocs allowed) ----------------
__device__ float g_S [(size_t)B_*2*S_*L_];    // scores (compact rows per (b,h))
__device__ float g_O2[(size_t)B_*S_*E_];      // out2d fp32
__device__ float g_lam;
__device__ unsigned char g_mask[B_*S_];
__device__ int g_mask_mode;
__device__ int g_idx[B_*S_];                  // compact i -> s (per batch)
__device__ int g_cnt[B_];                     // unmasked count per batch
__device__ float g_km[B_*E_];                 // mean over L of key2d
__device__ float g_mV[B_*E_];                 // mean over L of V rows

// bf16 split operand buffers (hi / lo)
__device__ bf16 g_qh[(size_t)B_*S_*E_],  g_ql[(size_t)B_*S_*E_];   // compacted query
__device__ bf16 g_kh[(size_t)B_*L_*E_],  g_kl[(size_t)B_*L_*E_];
__device__ bf16 g_Wqh[E_*E_], g_Wql[E_*E_], g_Wkh[E_*E_], g_Wkl[E_*E_];
__device__ bf16 g_Wvh[E_*E_], g_Wvl[E_*E_], g_Woh[E_*E_], g_Wol[E_*E_];
__device__ bf16 g_Qh[(size_t)B_*S_*E_],  g_Ql[(size_t)B_*S_*E_];   // compact Q (scaled)
__device__ bf16 g_Kh[(size_t)B_*L_*E_],  g_Kl[(size_t)B_*L_*E_];
__device__ bf16 g_Vth[(size_t)E_*B_*L_], g_Vtl[(size_t)E_*B_*L_];  // V^T [E][B*L]
__device__ bf16 g_dh[(size_t)B_*S_*L_],  g_dl[(size_t)B_*S_*L_];   // compact diff
__device__ bf16 g_rh[(size_t)B_*S_*E_],  g_rl[(size_t)B_*S_*E_];

// ---------------- small helpers ----------------
__device__ __forceinline__ float warpSum(float v) {
#pragma unroll
    for (int o = 16; o; o >>= 1) v += __shfl_xor_sync(0xffffffffu, v, o);
    return v;
}
__device__ __forceinline__ float warpMax(float v) {
#pragma unroll
    for (int o = 16; o; o >>= 1) v = fmaxf(v, __shfl_xor_sync(0xffffffffu, v, o));
    return v;
}
__device__ __forceinline__ void splitf(float x, bf16& h, bf16& l) {
    h = __float2bfloat16(x);
    l = __float2bfloat16(x - __bfloat162float(h));
}
__device__ __forceinline__ uint32_t s2u(const void* p) {
    return (uint32_t)__cvta_generic_to_shared(p);
}

// ---------------- tensor-core primitives (sm_80 baseline ISA) ----------------
__device__ __forceinline__ void ldsm_x4(uint32_t& r0, uint32_t& r1, uint32_t& r2,
                                        uint32_t& r3, uint32_t addr) {
    asm volatile("ldmatrix.sync.aligned.m8n8.x4.shared.b16 {%0,%1,%2,%3}, [%4];"
                 : "=r"(r0), "=r"(r1), "=r"(r2), "=r"(r3) : "r"(addr));
}
__device__ __forceinline__ void ldsm_x2(uint32_t& r0, uint32_t& r1, uint32_t addr) {
    asm volatile("ldmatrix.sync.aligned.m8n8.x2.shared.b16 {%0,%1}, [%2];"
                 : "=r"(r0), "=r"(r1) : "r"(addr));
}
__device__ __forceinline__ void mma16816(float* c, const uint32_t* a, const uint32_t* b) {
    asm volatile(
        "mma.sync.aligned.m16n8k16.row.col.f32.bf16.bf16.f32 "
        "{%0,%1,%2,%3}, {%4,%5,%6,%7}, {%8,%9}, {%0,%1,%2,%3};"
        : "+f"(c[0]), "+f"(c[1]), "+f"(c[2]), "+f"(c[3])
        : "r"(a[0]), "r"(a[1]), "r"(a[2]), "r"(a[3]), "r"(b[0]), "r"(b[1]));
}
__device__ __forceinline__ void cp16(uint32_t dst, const void* src) {
    asm volatile("cp.async.cg.shared.global [%0], [%1], 16;" :: "r"(dst), "l"(src));
}

// ---------------- GEMM config ----------------
#define BM 128
#define BN 128
#define BKT 32
#define SROW 40   // padded smem row stride (elems)

// C[M,N] = alpha * sum over 3 passes of Ap[M,K] @ Bp[N,K]^T  (bf16 in, fp32 accum)
// passes: (Ahi,Bhi), (Alo,Bhi), (Ahi,Blo)
// mode 0: fp32 -> Cf.  mode 1: bf16 split -> Ohi/Olo.  mode 2: bf16 split transposed.
// cnts (per zo): valid output rows; blocks with m0 >= cnts[zo] exit; row writes guarded.
// rowmap (per zo, stride S_): output row scatter (mode 0 only).
__global__ void __launch_bounds__(256, 2)
gemm3_kernel(const bf16* __restrict__ Ahi, const bf16* __restrict__ Alo,
             const bf16* __restrict__ Bhi, const bf16* __restrict__ Blo,
             float* __restrict__ Cf, bf16* __restrict__ Ohi, bf16* __restrict__ Olo,
             int K, int lda, int ldb, int ldout,
             int zdiv, long long sAo, long long sAi, long long sBo, long long sBi,
             long long sCo, long long sCi, float alpha, int mode,
             const int* __restrict__ cnts, const int* __restrict__ rowmap)
{
    __shared__ __align__(16) bf16 sA[2][BM * SROW];
    __shared__ __align__(16) bf16 sB[2][BN * SROW];

    const int tid  = threadIdx.x;
    const int lane = tid & 31;
    const int wid  = tid >> 5;
    const int wm   = wid & 1;
    const int wn   = wid >> 1;
    const int m0 = blockIdx.y * BM;
    const int n0 = blockIdx.x * BN;
    const int z  = blockIdx.z;
    const int zo = z / zdiv, zi = z - zo * zdiv;

    const int cnt = cnts ? cnts[zo] : 0x7fffffff;
    if (m0 >= cnt) return;

    const long long aoff = zo * sAo + zi * sAi;
    const long long boff = zo * sBo + zi * sBi;
    const long long coff = zo * sCo + zi * sCi;
    Ahi += aoff; Alo += aoff; Bhi += boff; Blo += boff;

    const int ktiles = K / BKT;
    const int total  = 3 * ktiles;

    float acc[4][4][4];
#pragma unroll
    for (int mi = 0; mi < 4; mi++)
#pragma unroll
        for (int ni = 0; ni < 4; ni++)
#pragma unroll
            for (int r = 0; r < 4; r++) acc[mi][ni][r] = 0.f;

    auto issue = [&](int it, int buf) {
        const int p  = it / ktiles;
        const int kt = it - p * ktiles;
        const bf16* Ap = ((p == 1) ? Alo : Ahi) + (long long)m0 * lda + kt * BKT;
        const bf16* Bp = ((p == 2) ? Blo : Bhi) + (long long)n0 * ldb + kt * BKT;
#pragma unroll
        for (int i = 0; i < 2; i++) {
            int u = tid + i * 256;
            int row = u >> 2, kc = (u & 3) * 8;
            cp16(s2u(&sA[buf][row * SROW + kc]), Ap + (long long)row * lda + kc);
            cp16(s2u(&sB[buf][row * SROW + kc]), Bp + (long long)row * ldb + kc);
        }
        asm volatile("cp.async.commit_group;" ::: "memory");
    };

    issue(0, 0);
    for (int it = 0; it < total; it++) {
        const int cur = it & 1;
        if (it + 1 < total) {
            issue(it + 1, cur ^ 1);
            asm volatile("cp.async.wait_group 1;" ::: "memory");
        } else {
            asm volatile("cp.async.wait_group 0;" ::: "memory");
        }
        __syncthreads();

        const bf16* sa = sA[cur];
        const bf16* sb = sB[cur];
#pragma unroll
        for (int ks = 0; ks < 2; ks++) {
            uint32_t af[4][4], bfr[4][2];
            const int arow = wm * 64 + (lane & 15);
            const int acol = ks * 16 + (lane >> 4) * 8;
#pragma unroll
            for (int mi = 0; mi < 4; mi++)
                ldsm_x4(af[mi][0], af[mi][1], af[mi][2], af[mi][3],
                        s2u(sa + (arow + mi * 16) * SROW + acol));
            const int brow = wn * 32 + (lane & 7);
            const int bcol = ks * 16 + ((lane >> 3) & 1) * 8;
#pragma unroll
            for (int ni = 0; ni < 4; ni++)
                ldsm_x2(bfr[ni][0], bfr[ni][1],
                        s2u(sb + (brow + ni * 8) * SROW + bcol));
#pragma unroll
            for (int mi = 0; mi < 4; mi++)
#pragma unroll
                for (int ni = 0; ni < 4; ni++)
                    mma16816(acc[mi][ni], af[mi], bfr[ni]);
        }
        __syncthreads();
    }

    // ---- epilogue ----
    const int g = lane >> 2, tg = lane & 3;
    const int* rmap = rowmap ? (rowmap + (long long)zo * S_) : nullptr;
#pragma unroll
    for (int mi = 0; mi < 4; mi++) {
#pragma unroll
        for (int ni = 0; ni < 4; ni++) {
            const int r0  = m0 + wm * 64 + mi * 16 + g;
            const int r1  = r0 + 8;
            const int col = n0 + wn * 32 + ni * 8 + 2 * tg;
            float c0 = alpha * acc[mi][ni][0];
            float c1 = alpha * acc[mi][ni][1];
            float c2 = alpha * acc[mi][ni][2];
            float c3 = alpha * acc[mi][ni][3];
            if (mode == 0) {
                if (r0 < cnt) {
                    int ro = rmap ? rmap[r0] : r0;
                    *(float2*)(Cf + coff + (long long)ro * ldout + col) = make_float2(c0, c1);
                }
                if (r1 < cnt) {
                    int ro = rmap ? rmap[r1] : r1;
                    *(float2*)(Cf + coff + (long long)ro * ldout + col) = make_float2(c2, c3);
                }
            } else if (mode == 1) {
                bf16 h0, l0, h1, l1, h2, l2, h3, l3;
                splitf(c0, h0, l0); splitf(c1, h1, l1);
                splitf(c2, h2, l2); splitf(c3, h3, l3);
                if (r0 < cnt) {
                    __nv_bfloat162 hv; hv.x = h0; hv.y = h1;
                    __nv_bfloat162 lv; lv.x = l0; lv.y = l1;
                    *(__nv_bfloat162*)(Ohi + coff + (long long)r0 * ldout + col) = hv;
                    *(__nv_bfloat162*)(Olo + coff + (long long)r0 * ldout + col) = lv;
                }
                if (r1 < cnt) {
                    __nv_bfloat162 hv; hv.x = h2; hv.y = h3;
                    __nv_bfloat162 lv; lv.x = l2; lv.y = l3;
                    *(__nv_bfloat162*)(Ohi + coff + (long long)r1 * ldout + col) = hv;
                    *(__nv_bfloat162*)(Olo + coff + (long long)r1 * ldout + col) = lv;
                }
            } else {
                bf16 h, l;
                splitf(c0, h, l);
                Ohi[coff + (long long)col * ldout + r0] = h;
                Olo[coff + (long long)col * ldout + r0] = l;
                splitf(c1, h, l);
                Ohi[coff + (long long)(col + 1) * ldout + r0] = h;
                Olo[coff + (long long)(col + 1) * ldout + r0] = l;
                splitf(c2, h, l);
                Ohi[coff + (long long)col * ldout + r1] = h;
                Olo[coff + (long long)col * ldout + r1] = l;
                splitf(c3, h, l);
                Ohi[coff + (long long)(col + 1) * ldout + r1] = h;
                Olo[coff + (long long)(col + 1) * ldout + r1] = l;
            }
        }
    }
}

// ---------------- mask dtype detection + canonicalization ----------------
__global__ void mask_detect_kernel(const unsigned char* __restrict__ m) {
    int t = threadIdx.x;
    int nz1 = 0, nz23 = 0;
    for (int i = t; i < B_ * S_; i += 256) {
        unsigned char v = m[i];
        int r = i & 3;
        if (v) {
            if (r == 1) nz1 = 1;
            if (r == 2 || r == 3) nz23 = 1;
        }
    }
    nz1  = __syncthreads_or(nz1);
    nz23 = __syncthreads_or(nz23);
    if (t == 0) g_mask_mode = nz1 ? 0 : (nz23 ? 2 : 1);
}
__global__ void mask_convert_kernel(const void* __restrict__ m) {
    int i = blockIdx.x * 256 + threadIdx.x;
    int mode = g_mask_mode;
    unsigned char v;
    if (mode == 0)      v = ((const unsigned char*)m)[i] != 0;
    else if (mode == 1) v = ((const int*)m)[i] != 0;
    else                v = ((const float*)m)[i] != 0.0f;
    g_mask[i] = v;
}

// ---------------- per-batch compaction of unmasked rows ----------------
__global__ void compact_kernel() {
    const int b = blockIdx.x, s = threadIdx.x;     // 1024 threads
    const int lane = s & 31, w = s >> 5;
    __shared__ int wcnt[32];
    int f = g_mask[b * S_ + s] ? 1 : 0;
    unsigned bal = __ballot_sync(0xffffffffu, f);
    int lanePre = __popc(bal & ((1u << lane) - 1u));
    if (lane == 0) wcnt[w] = __popc(bal);
    __syncthreads();
    if (w == 0) {
        int v = wcnt[lane];
#pragma unroll
        for (int o = 1; o < 32; o <<= 1) {
            int u = __shfl_up_sync(0xffffffffu, v, o);
            if (lane >= o) v += u;
        }
        wcnt[lane] = v;   // inclusive scan
    }
    __syncthreads();
    int base = (w == 0) ? 0 : wcnt[w - 1];
    if (f) g_idx[b * S_ + base + lanePre] = s;
    if (s == 0) g_cnt[b] = wcnt[31];
}

// ---------------- gather + split query rows (compact) ----------------
__global__ void gather_split_q(const float* __restrict__ q) {
    const int blk = blockIdx.x;               // B*S
    const int b = blk >> 10, i = blk & (S_ - 1);
    if (i >= g_cnt[b]) return;
    const int s = g_idx[b * S_ + i];
    const float* src = q + ((size_t)b * S_ + s) * E_;
    bf16* dh = g_qh + ((size_t)b * S_ + i) * E_;
    bf16* dl = g_ql + ((size_t)b * S_ + i) * E_;
    const int t = threadIdx.x;                // 128
#pragma unroll
    for (int j = 0; j < 4; j++) {
        bf16 h, l; splitf(src[t + j * 128], h, l);
        dh[t + j * 128] = h; dl[t + j * 128] = l;
    }
}

// ---------------- elementwise split (fp32 -> bf16 hi/lo) ----------------
__global__ void split_kernel(const float* __restrict__ x, bf16* __restrict__ hi,
                             bf16* __restrict__ lo, long long n) {
    long long i = (long long)blockIdx.x * 256 + threadIdx.x;
    long long stride = (long long)gridDim.x * 256;
    for (; i < n; i += stride) {
        bf16 h, l; splitf(x[i], h, l);
        hi[i] = h; lo[i] = l;
    }
}
// split + transpose for 512x512 weights: T[n][k] = W[k][n]
__global__ void splitT_W_kernel(const float* __restrict__ W, bf16* __restrict__ Thi,
                                bf16* __restrict__ Tlo) {
    int idx = blockIdx.x * 256 + threadIdx.x;
    int n = idx >> 9, k = idx & 511;
    bf16 h, l; splitf(W[k * E_ + n], h, l);
    Thi[(long long)n * E_ + k] = h;
    Tlo[(long long)n * E_ + k] = l;
}

// ---------------- lambda ----------------
__global__ void lam_kernel(const float* __restrict__ lq1, const float* __restrict__ lk1,
                           const float* __restrict__ lq2, const float* __restrict__ lk2)
{
    __shared__ float sm[16];
    int t = threadIdx.x;
    float p1 = lq1[t] * lk1[t];
    float p2 = lq2[t] * lk2[t];
    p1 = warpSum(p1);
    p2 = warpSum(p2);
    int w = t >> 5, l = t & 31;
    if (l == 0) { sm[w] = p1; sm[8 + w] = p2; }
    __syncthreads();
    if (t == 0) {
        float d1 = 0.f, d2 = 0.f;
#pragma unroll
        for (int i = 0; i < 8; i++) { d1 += sm[i]; d2 += sm[8 + i]; }
        g_lam = expf(d1) - expf(d2) + LAMBDA_INIT_;
    }
}

// ---------------- key mean + masked out2d row value ----------------
__global__ void keymean_kernel(const float* __restrict__ key) {
    int id = blockIdx.x * 128 + threadIdx.x;   // B*E
    int b = id >> 9, e = id & 511;
    const float* p = key + (size_t)b * L_ * E_ + e;
    float s = 0.f;
    for (int l = 0; l < L_; l++) s += p[(size_t)l * E_];
    g_km[id] = s * (1.0f / (float)L_);
}
__global__ void mV_kernel(const float* __restrict__ Wv) {
    int id = blockIdx.x * 128 + threadIdx.x;   // B*E
    int b = id >> 9, e = id & 511;
    float s = 0.f;
    const float* km = g_km + b * E_;
    for (int k = 0; k < E_; k++) s += km[k] * Wv[k * E_ + e];
    g_mV[id] = s;
}

// ---------------- fused dual softmax + lambda-diff (compact rows only) ----------------
__global__ void __launch_bounds__(256)
softmax_diff_kernel(const float* __restrict__ sc, float* __restrict__ diff)
{
    __shared__ float sm[8];
    const int blk = blockIdx.x;                 // b*S + i (compact)
    const int b = blk >> 10;
    const int i = blk & (S_ - 1);
    if (i >= g_cnt[b]) return;
    const int s = g_idx[b * S_ + i];
    const int t = threadIdx.x;
    const int w = t >> 5, l = t & 31;
    const float lam = g_lam;
    float* out = diff + ((size_t)b * S_ + s) * L_;        // scattered fp32 output
    bf16* dh = g_dh + ((size_t)b * S_ + i) * L_;          // compact split for GEMM
    bf16* dl = g_dl + ((size_t)b * S_ + i) * L_;

    const float* r0 = sc + ((size_t)(2 * b + 0) * S_ + i) * L_;
    const float* r1 = sc + ((size_t)(2 * b + 1) * S_ + i) * L_;
    float e0[8], e1[8];

    float mx = -1e30f;
#pragma unroll
    for (int j = 0; j < 8; j++) { e0[j] = r0[t + j * 256]; mx = fmaxf(mx, e0[j]); }
    mx = warpMax(mx);
    if (l == 0) sm[w] = mx;
    __syncthreads();
#pragma unroll
    for (int j = 0; j < 8; j++) mx = fmaxf(mx, sm[j]);
    float sum0 = 0.f;
#pragma unroll
    for (int j = 0; j < 8; j++) { e0[j] = __expf(e0[j] - mx); sum0 += e0[j]; }
    sum0 = warpSum(sum0);
    __syncthreads();
    if (l == 0) sm[w] = sum0;
    __syncthreads();
    sum0 = 0.f;
#pragma unroll
    for (int j = 0; j < 8; j++) sum0 += sm[j];
    const float inv0 = 1.0f / sum0;

    float mx1 = -1e30f;
#pragma unroll
    for (int j = 0; j < 8; j++) { e1[j] = r1[t + j * 256]; mx1 = fmaxf(mx1, e1[j]); }
    mx1 = warpMax(mx1);
    __syncthreads();
    if (l == 0) sm[w] = mx1;
    __syncthreads();
#pragma unroll
    for (int j = 0; j < 8; j++) mx1 = fmaxf(mx1, sm[j]);
    float sum1 = 0.f;
#pragma unroll
    for (int j = 0; j < 8; j++) { e1[j] = __expf(e1[j] - mx1); sum1 += e1[j]; }
    sum1 = warpSum(sum1);
    __syncthreads();
    if (l == 0) sm[w] = sum1;
    __syncthreads();
    sum1 = 0.f;
#pragma unroll
    for (int j = 0; j < 8; j++) sum1 += sm[j];
    const float inv1 = 1.0f / sum1;

#pragma unroll
    for (int j = 0; j < 8; j++) {
        float v = e0[j] * inv0 - lam * (e1[j] * inv1);
        out[t + j * 256] = v;
        bf16 h, lo; splitf(v, h, lo);
        dh[t + j * 256] = h; dl[t + j * 256] = lo;
    }
}

// ---------------- masked rows: diff const + out2d = (1-lam)*meanV[b] ----------------
__global__ void __launch_bounds__(256)
fill_masked_kernel(float* __restrict__ diff)
{
    const int bs = blockIdx.x;
    if (g_mask[bs]) return;
    const int b = bs >> 10;
    const int t = threadIdx.x;
    const float oml = 1.0f - g_lam;
    const float v = oml * (1.0f / (float)L_);
    float* dr = diff + (size_t)bs * L_;
#pragma unroll
    for (int j = 0; j < 8; j++) dr[t + j * 256] = v;
    float* orow = g_O2 + (size_t)bs * E_;
    orow[t]       = oml * g_mV[b * E_ + t];
    orow[t + 256] = oml * g_mV[b * E_ + t + 256];
}

// ---------------- RMSNorm * gamma * 0.8 -> bf16 split ----------------
__global__ void __launch_bounds__(128)
rmsnorm_kernel(const float* __restrict__ x, const float* __restrict__ gamma)
{
    __shared__ float sm[4];
    const int row = blockIdx.x;
    const int t = threadIdx.x;
    const float4 v = ((const float4*)(x + (size_t)row * E_))[t];
    float ss = v.x * v.x + v.y * v.y + v.z * v.z + v.w * v.w;
    ss = warpSum(ss);
    int w = t >> 5, l = t & 31;
    if (l == 0) sm[w] = ss;
    __syncthreads();
    ss = sm[0] + sm[1] + sm[2] + sm[3];
    float r = rsqrtf(ss * (1.0f / (float)E_) + 1e-5f) * ONE_MINUS_LI_;
    float4 g = ((const float4*)gamma)[t];
    float y[4] = {v.x * r * g.x, v.y * r * g.y, v.z * r * g.z, v.w * r * g.w};
    bf16* oh = g_rh + (size_t)row * E_ + t * 4;
    bf16* ol = g_rl + (size_t)row * E_ + t * 4;
#pragma unroll
    for (int j = 0; j < 4; j++) {
        bf16 h, lo; splitf(y[j], h, lo);
        oh[j] = h; ol[j] = lo;
    }
}

// ---------------- launch ----------------
extern "C" void kernel_launch(void* const* d_in, const int* in_sizes, int n_in,
                              void* d_out, int out_size)
{
    const float* query = (const float*)d_in[0];
    const float* key   = (const float*)d_in[1];
    const void*  mask  = d_in[2];
    const float* Wq    = (const float*)d_in[3];
    const float* Wk    = (const float*)d_in[4];
    const float* Wv    = (const float*)d_in[5];
    const float* Wo    = (const float*)d_in[6];
    const float* lq1   = (const float*)d_in[7];
    const float* lk1   = (const float*)d_in[8];
    const float* lq2   = (const float*)d_in[9];
    const float* lk2   = (const float*)d_in[10];
    const float* gamma = (const float*)d_in[11];

    float* out  = (float*)d_out;
    float* diff = out + (size_t)B_ * S_ * E_;

    float *Sp, *Op;
    int *idxP, *cntP;
    bf16 *qh,*ql,*kh,*kl,*Wqh,*Wql,*Wkh,*Wkl,*Wvh,*Wvl,*Woh,*Wol;
    bf16 *Qh,*Ql,*Kh,*Kl,*Vth,*Vtl,*dh,*dl,*rh,*rl;
    cudaGetSymbolAddress((void**)&Sp,  g_S);
    cudaGetSymbolAddress((void**)&Op,  g_O2);
    cudaGetSymbolAddress((void**)&idxP, g_idx);
    cudaGetSymbolAddress((void**)&cntP, g_cnt);
    cudaGetSymbolAddress((void**)&qh,  g_qh);  cudaGetSymbolAddress((void**)&ql,  g_ql);
    cudaGetSymbolAddress((void**)&kh,  g_kh);  cudaGetSymbolAddress((void**)&kl,  g_kl);
    cudaGetSymbolAddress((void**)&Wqh, g_Wqh); cudaGetSymbolAddress((void**)&Wql, g_Wql);
    cudaGetSymbolAddress((void**)&Wkh, g_Wkh); cudaGetSymbolAddress((void**)&Wkl, g_Wkl);
    cudaGetSymbolAddress((void**)&Wvh, g_Wvh); cudaGetSymbolAddress((void**)&Wvl, g_Wvl);
    cudaGetSymbolAddress((void**)&Woh, g_Woh); cudaGetSymbolAddress((void**)&Wol, g_Wol);
    cudaGetSymbolAddress((void**)&Qh,  g_Qh);  cudaGetSymbolAddress((void**)&Ql,  g_Ql);
    cudaGetSymbolAddress((void**)&Kh,  g_Kh);  cudaGetSymbolAddress((void**)&Kl,  g_Kl);
    cudaGetSymbolAddress((void**)&Vth, g_Vth); cudaGetSymbolAddress((void**)&Vtl, g_Vtl);
    cudaGetSymbolAddress((void**)&dh,  g_dh);  cudaGetSymbolAddress((void**)&dl,  g_dl);
    cudaGetSymbolAddress((void**)&rh,  g_rh);  cudaGetSymbolAddress((void**)&rl,  g_rl);

    const long long SE = (long long)S_ * E_;
    const long long LE = (long long)L_ * E_;
    const long long SL = (long long)S_ * L_;
    const int BL = B_ * L_;   // 32768

    // mask, compaction, lambda
    mask_detect_kernel<<<1, 256>>>((const unsigned char*)mask);
    mask_convert_kernel<<<(B_ * S_) / 256, 256>>>(mask);
    compact_kernel<<<B_, S_>>>();
    lam_kernel<<<1, 256>>>(lq1, lk1, lq2, lk2);

    // input splits
    gather_split_q<<<B_ * S_, 128>>>(query);
    split_kernel<<<4096, 256>>>(key, kh, kl, (long long)B_ * L_ * E_);
    splitT_W_kernel<<<(E_ * E_) / 256, 256>>>(Wq, Wqh, Wql);
    splitT_W_kernel<<<(E_ * E_) / 256, 256>>>(Wk, Wkh, Wkl);
    splitT_W_kernel<<<(E_ * E_) / 256, 256>>>(Wv, Wvh, Wvl);
    splitT_W_kernel<<<(E_ * E_) / 256, 256>>>(Wo, Woh, Wol);

    // masked-row closed form ingredients
    keymean_kernel<<<(B_ * E_) / 128, 128>>>(key);
    mV_kernel<<<(B_ * E_) / 128, 128>>>(Wv);

    // Q proj (compact rows, per-batch z): -> split Qs (pre-scaled)
    gemm3_kernel<<<dim3(E_ / BN, S_ / BM, B_), 256>>>(
        qh, ql, Wqh, Wql, nullptr, Qh, Ql,
        E_, E_, E_, E_, 1, SE, 0, 0, 0, SE, 0, SCALE_, 1, cntP, nullptr);

    // K proj -> split Ks (full)
    gemm3_kernel<<<dim3(E_ / BN, (B_ * L_) / BM, 1), 256>>>(
        kh, kl, Wkh, Wkl, nullptr, Kh, Kl,
        E_, E_, E_, E_, 1, 0, 0, 0, 0, 0, 0, 1.0f, 1, nullptr, nullptr);

    // V proj -> transposed split Vt [E][B*L] (full)
    gemm3_kernel<<<dim3(E_ / BN, (B_ * L_) / BM, 1), 256>>>(
        kh, kl, Wvh, Wvl, nullptr, Vth, Vtl,
        E_, E_, E_, BL, 1, 0, 0, 0, 0, 0, 0, 1.0f, 2, nullptr, nullptr);

    // scores[b,h] = Qc[b,:,hHD:] @ K[b,:,hHD:]^T -> g_S (compact rows)
    gemm3_kernel<<<dim3(L_ / BN, S_ / BM, B_ * 2), 256>>>(
        Qh, Ql, Kh, Kl, Sp, nullptr, nullptr,
        HD_, E_, E_, L_, 2, SE, HD_, LE, HD_, 2 * SL, SL, 1.0f, 0, cntP, nullptr);

    // softmax + diff on compact rows (fp32 scattered to d_out, split compact)
    softmax_diff_kernel<<<B_ * S_, 256>>>(Sp, diff);

    // masked rows: diff const + out2d closed form
    fill_masked_kernel<<<B_ * S_, 256>>>(diff);

    // out2d[b] = diff_c[b] @ V[b] -> g_O2 fp32, rows scattered via g_idx
    gemm3_kernel<<<dim3(E_ / BN, S_ / BM, B_), 256>>>(
        dh, dl, Vth, Vtl, Op, nullptr, nullptr,
        L_, L_, BL, E_, 1, SL, 0, L_, 0, SE, 0, 1.0f, 0, cntP, idxP);

    // RMSNorm * gamma * 0.8 -> split rms (full S)
    rmsnorm_kernel<<<B_ * S_, 128>>>(Op, gamma);

    // out = rms @ Wo^T -> d_out fp32 (full)
    gemm3_kernel<<<dim3(E_ / BN, (B_ * S_) / BM, 1), 256>>>(
        rh, rl, Woh, Wol, out, nullptr, nullptr,
        E_, E_, E_, E_, 1, 0, 0, 0, 0, 0, 0, 1.0f, 0, nullptr, nullptr);
}